// round 14
// baseline (speedup 1.0000x reference)
#include <cuda_runtime.h>
#include <math_constants.h>

#define BB 4
#define NN 2048
#define IND 256
#define OUTD 256
#define HH 4
#define HD 64
#define TI 32
#define TJ 32

// ---------------- scratch ----------------
// g_Wh is stored PERMUTED within each head: element (nt,g) [col = nt*8+g] lives
// at position Q(g)*8+nt, Q = {0,2,1,3,4,6,5,7}. Only attn reads it.
__device__ float g_Wh[BB * NN * OUTD];
__device__ float g_multi[BB * NN * OUTD];
__device__ float g_part[2][BB * NN * OUTD];
__device__ float g_lpart[2][BB * HH * NN];
__device__ float g_ssrc[BB * HH * NN];
__device__ float g_esrP[BB * HH * NN];
__device__ float g_esrN[BB * HH * NN];
__device__ float4 g_pack[BB * HH * NN];
__device__ float g_WcatH[IND * OUTD];
__device__ float g_WcatL[IND * OUTD];
__device__ float g_WoutTH[OUTD * OUTD];
__device__ float g_WoutTL[OUTD * OUTD];

__device__ __forceinline__ unsigned tf32r(float x) {
    unsigned u;
    asm("cvt.rna.tf32.f32 %0, %1;" : "=r"(u) : "f"(x));
    return u;
}
__device__ __forceinline__ void cpasync16(unsigned saddr, const void* g) {
    asm volatile("cp.async.cg.shared.global [%0], [%1], 16;" :: "r"(saddr), "l"(g));
}
__device__ __forceinline__ void cpcommit() {
    asm volatile("cp.async.commit_group;" ::: "memory");
}
__device__ __forceinline__ void cpwait1() {
    asm volatile("cp.async.wait_group 1;" ::: "memory");
}
#define MMA_TF32(accv, af, b0, b1)                                              \
    asm volatile(                                                               \
        "mma.sync.aligned.m16n8k8.row.col.f32.tf32.tf32.f32 "                   \
        "{%0,%1,%2,%3}, {%4,%5,%6,%7}, {%8,%9}, {%0,%1,%2,%3};"                 \
        : "+f"(accv[0]), "+f"(accv[1]), "+f"(accv[2]), "+f"(accv[3])            \
        : "r"(af[0]), "r"(af[1]), "r"(af[2]), "r"(af[3]), "r"(b0), "r"(b1))

// ---------------- weight re-layout + tf32 hi/lo split ----------------
__global__ void transpose_kernel(const float* __restrict__ W,
                                 const float* __restrict__ Wout) {
    int idx = blockIdx.x * 256 + threadIdx.x;
    int k = idx >> 8, cc = idx & 255;
    int h = cc >> 6, d = cc & 63;
    float wv = W[h * (IND * HD) + k * HD + d];
    unsigned wh = tf32r(wv);
    g_WcatH[idx] = __uint_as_float(wh);
    g_WcatL[idx] = __uint_as_float(tf32r(wv - __uint_as_float(wh)));
    float ov = Wout[cc * 256 + k];
    unsigned oh = tf32r(ov);
    g_WoutTH[k * 256 + cc] = __uint_as_float(oh);
    g_WoutTL[k * 256 + cc] = __uint_as_float(tf32r(ov - __uint_as_float(oh)));
}

// ---------------- tf32x3 MMA GEMM: 64x64 CTA tile ----------------
// FUSE=true (gemm_wh): writes g_Wh in permuted layout + emits s-logit tables.
template <bool FUSE>
__device__ __forceinline__ void mma_gemm_body(const float* __restrict__ A,
                                              const float* __restrict__ BH,
                                              const float* __restrict__ BL,
                                              float* __restrict__ C,
                                              const float* __restrict__ bias,
                                              bool has_bias,
                                              const float* __restrict__ avec) {
    __shared__ __align__(16) float As[2][64][20];
    __shared__ __align__(16) float BsH[2][16][72];
    __shared__ __align__(16) float BsL[2][16][72];
    __shared__ float aS[128];
    __shared__ float sred[2][64][2];

    int t = threadIdx.x, lane = t & 31, w = t >> 5;
    int g = lane >> 2, c = lane & 3;
    int mw = w & 3, nw = w >> 2;
    int m0 = blockIdx.y * 64, n0 = blockIdx.x * 64;
    int mb = mw * 16, nb = nw * 32;

    if (FUSE && t < 128) aS[t] = avec[t];

    unsigned asb = (unsigned)__cvta_generic_to_shared(&As[0][0][0]);
    unsigned bhb = (unsigned)__cvta_generic_to_shared(&BsH[0][0][0]);
    unsigned blb = (unsigned)__cvta_generic_to_shared(&BsL[0][0][0]);

    auto stage = [&](int k0, int buf) {
        {
            int row = t >> 2, seg = t & 3;
            cpasync16(asb + buf * 5120 + row * 80 + seg * 16,
                      A + (size_t)(m0 + row) * 256 + k0 + seg * 4);
        }
        {
            int row = t >> 4, seg = t & 15;
            cpasync16(bhb + buf * 4608 + row * 288 + seg * 16,
                      BH + (size_t)(k0 + row) * 256 + n0 + seg * 4);
            cpasync16(blb + buf * 4608 + row * 288 + seg * 16,
                      BL + (size_t)(k0 + row) * 256 + n0 + seg * 4);
        }
    };

    float acc[4][4] = {};

    stage(0, 0);
    cpcommit();
    for (int s = 0; s < 16; s++) {
        int buf = s & 1;
        if (s < 15) stage((s + 1) * 16, buf ^ 1);
        cpcommit();
        cpwait1();
        __syncthreads();
#pragma unroll
        for (int kk = 0; kk < 16; kk += 8) {
            unsigned ah[4], al[4];
#pragma unroll
            for (int q = 0; q < 4; q++) {
                int rr = mb + g + (q & 1) * 8;
                int ck = kk + c + (q >> 1) * 4;
                float v = As[buf][rr][ck];
                unsigned hb = tf32r(v);
                ah[q] = hb;
                al[q] = tf32r(v - __uint_as_float(hb));
            }
#pragma unroll
            for (int ni = 0; ni < 4; ni++) {
                int col = nb + ni * 8 + g;
                unsigned bh0 = __float_as_uint(BsH[buf][kk + c][col]);
                unsigned bh1 = __float_as_uint(BsH[buf][kk + c + 4][col]);
                unsigned bl0 = __float_as_uint(BsL[buf][kk + c][col]);
                unsigned bl1 = __float_as_uint(BsL[buf][kk + c + 4][col]);
                MMA_TF32(acc[ni], al, bh0, bh1);
                MMA_TF32(acc[ni], ah, bl0, bl1);
                MMA_TF32(acc[ni], ah, bh0, bh1);
            }
        }
        __syncthreads();
    }

    if (!FUSE) {
#pragma unroll
        for (int ni = 0; ni < 4; ni++) {
            int col = n0 + nb + ni * 8 + 2 * c;
            float bx = 0.f, by = 0.f;
            if (has_bias) {
                float2 bv = *(const float2*)&bias[col];
                bx = bv.x; by = bv.y;
            }
            int r0 = m0 + mb + g;
            float2 v0 = {acc[ni][0] + bx, acc[ni][1] + by};
            float2 v1 = {acc[ni][2] + bx, acc[ni][3] + by};
            *(float2*)&C[(size_t)r0 * 256 + col] = v0;
            *(float2*)&C[(size_t)(r0 + 8) * 256 + col] = v1;
        }
    } else {
        // permuted store: d = nb+ni*8+2c (+1) -> pos Q(d&7)*8 + d/8; Q(2c)=((c<<1)&4)|(c&1)
        int r0 = m0 + mb + g;
        float* base0 = &C[(size_t)r0 * 256 + n0];
        float* base1 = &C[(size_t)(r0 + 8) * 256 + n0];
#pragma unroll
        for (int ni = 0; ni < 4; ni++) {
            int nt = (nb >> 3) + ni;
            int p0 = (((c << 1) & 4) | (c & 1)) * 8 + nt;
            base0[p0]      = acc[ni][0];
            base0[p0 + 16] = acc[ni][1];   // Q(2c+1) = Q(2c)+2 -> +16 floats
            base1[p0]      = acc[ni][2];
            base1[p0 + 16] = acc[ni][3];
        }
        // ---- fused s-logits (reads accumulators; layout-independent) ----
        float ps0 = 0.f, ps1 = 0.f, pd0 = 0.f, pd1 = 0.f;
#pragma unroll
        for (int ni = 0; ni < 4; ni++) {
            int c0 = nb + ni * 8 + 2 * c;
            float as0 = aS[c0], as1 = aS[c0 + 1];
            float ad0 = aS[64 + c0], ad1 = aS[64 + c0 + 1];
            ps0 += acc[ni][0] * as0 + acc[ni][1] * as1;
            pd0 += acc[ni][0] * ad0 + acc[ni][1] * ad1;
            ps1 += acc[ni][2] * as0 + acc[ni][3] * as1;
            pd1 += acc[ni][2] * ad0 + acc[ni][3] * ad1;
        }
        ps0 += __shfl_xor_sync(0xffffffffu, ps0, 1);
        ps0 += __shfl_xor_sync(0xffffffffu, ps0, 2);
        pd0 += __shfl_xor_sync(0xffffffffu, pd0, 1);
        pd0 += __shfl_xor_sync(0xffffffffu, pd0, 2);
        ps1 += __shfl_xor_sync(0xffffffffu, ps1, 1);
        ps1 += __shfl_xor_sync(0xffffffffu, ps1, 2);
        pd1 += __shfl_xor_sync(0xffffffffu, pd1, 1);
        pd1 += __shfl_xor_sync(0xffffffffu, pd1, 2);
        if (c == 0) {
            sred[nw][mb + g][0] = ps0;
            sred[nw][mb + g][1] = pd0;
            sred[nw][mb + g + 8][0] = ps1;
            sred[nw][mb + g + 8][1] = pd1;
        }
        __syncthreads();
        if (t < 64) {
            float ss = sred[0][t][0] + sred[1][t][0];
            float sd = sred[0][t][1] + sred[1][t][1];
            int node = m0 + t;
            int b = node >> 11, n = node & 2047;
            int h = blockIdx.x;
            int idx = b * (HH * NN) + h * NN + n;
            g_ssrc[idx] = ss;
            g_esrP[idx] = __expf(ss);
            g_esrN[idx] = __expf(0.2f * ss);
            float4 pk = {sd, __expf(sd), __expf(0.2f * sd), 0.f};
            g_pack[idx] = pk;
        }
    }
}

__global__ void __launch_bounds__(256, 3) gemm_wh(const float* __restrict__ x,
                                                  const float* __restrict__ a) {
    mma_gemm_body<true>(x, g_WcatH, g_WcatL, g_Wh, nullptr, false, a);
}
__global__ void __launch_bounds__(256, 3) gemm_out(float* __restrict__ out,
                                                   const float* __restrict__ bout) {
    mma_gemm_body<false>(g_multi, g_WoutTH, g_WoutTL, out, bout, true, nullptr);
}

// ---------------- attention: split-j + permuted Wh (float4 B-frag loads) ----------------
__global__ void __launch_bounds__(128) attn_kernel(const int* __restrict__ adj) {
    __shared__ __align__(16) float  WhS[2][TJ][132];   // stride 132 -> phase banks 4c+8Q(g)+w all distinct
    __shared__ __align__(16) int    adjS[2][TJ][36];
    __shared__ float4 packS[2][2][TJ];

    int t = threadIdx.x;
    int lane = t & 31;
    int w = t >> 5;
    int hl = w & 1, is = w >> 1;
    int g = lane >> 2, c = lane & 3;

    int zz = blockIdx.z;
    int b = zz & (BB - 1);
    int jh2 = zz >> 2;
    int h0 = blockIdx.y * 2;
    int i0 = blockIdx.x * TI;
    int h = h0 + hl;

    int iA = i0 + is * 16 + g;
    int sbA = b * (HH * NN) + h * NN + iA;
    float siA = g_ssrc[sbA],     ePA = g_esrP[sbA],     eNA = g_esrN[sbA];
    float siB = g_ssrc[sbA + 8], ePB = g_esrP[sbA + 8], eNB = g_esrN[sbA + 8];

    float acc[8][4];
#pragma unroll
    for (int nt = 0; nt < 8; nt++)
#pragma unroll
        for (int q = 0; q < 4; q++) acc[nt][q] = 0.f;
    float leA = 0.f, leB = 0.f;

    const float* WhB = g_Wh + (size_t)b * NN * 256 + h0 * HD;
    const int* adjB = adj + ((size_t)(b * NN + i0)) * NN;
    const float4* packB = g_pack + b * (HH * NN);

    unsigned whsb  = (unsigned)__cvta_generic_to_shared(&WhS[0][0][0]);
    unsigned adjsb = (unsigned)__cvta_generic_to_shared(&adjS[0][0][0]);
    unsigned pksb  = (unsigned)__cvta_generic_to_shared(&packS[0][0][0]);
    const unsigned WHSZ = TJ * 132 * 4, ADSZ = TJ * 36 * 4, PKSZ = 2 * TJ * 16;

    int isg = is * 16 + g;
    int Qg = (g & 4) | ((g & 1) << 1) | ((g >> 1) & 1);
    int cQ = hl * 64 + Qg * 8;
    int tile0 = jh2 * (NN / TJ / 2);
    int tile1 = tile0 + NN / TJ / 2;

    auto stage = [&](int j0, int s) {
        unsigned wb = whsb + s * WHSZ;
#pragma unroll
        for (int k = 0; k < 8; k++) {
            int id = t + k * 128;
            int row = id >> 5, seg = id & 31;
            cpasync16(wb + row * 528 + seg * 16,
                      WhB + (size_t)(j0 + row) * 256 + seg * 4);
        }
        unsigned ab = adjsb + s * ADSZ;
#pragma unroll
        for (int k = 0; k < 2; k++) {
            int id = t + k * 128;
            int row = id >> 3, seg = id & 7;
            cpasync16(ab + row * 144 + seg * 16,
                      adjB + (size_t)row * NN + j0 + seg * 4);
        }
        if (t < 64) {
            int hh = t >> 5, jj = t & 31;
            cpasync16(pksb + s * PKSZ + t * 16,
                      packB + (h0 + hh) * NN + j0 + jj);
        }
    };

    stage(tile0 * TJ, 0);
    cpcommit();

    for (int tile = tile0; tile < tile1; tile++) {
        int s = tile & 1;
        if (tile + 1 < tile1) stage((tile + 1) * TJ, s ^ 1);
        cpcommit();
        cpwait1();
        __syncthreads();

#pragma unroll
        for (int kc = 0; kc < 4; kc++) {
            int j1 = kc * 8 + c, j2 = j1 + 4;
            float4 P1 = packS[s][hl][j1];
            float4 P2 = packS[s][hl][j2];
            int aA1 = adjS[s][isg][j1],     aA2 = adjS[s][isg][j2];
            int aB1 = adjS[s][isg + 8][j1], aB2 = adjS[s][isg + 8][j2];
            float e0 = (siA + P1.x > 0.f) ? ePA * P1.y : eNA * P1.z;
            float e1 = (siB + P1.x > 0.f) ? ePB * P1.y : eNB * P1.z;
            float e2 = (siA + P2.x > 0.f) ? ePA * P2.y : eNA * P2.z;
            float e3 = (siB + P2.x > 0.f) ? ePB * P2.y : eNB * P2.z;
            e0 = aA1 ? e0 : 0.f;
            e1 = aB1 ? e1 : 0.f;
            e2 = aA2 ? e2 : 0.f;
            e3 = aB2 ? e3 : 0.f;
            leA += e0 + e2;
            leB += e1 + e3;
            unsigned a0 = tf32r(e0), a1 = tf32r(e1), a2 = tf32r(e2), a3 = tf32r(e3);
            unsigned af[4] = {a0, a1, a2, a3};
            const float* r1 = &WhS[s][j1][cQ];
            const float* r2 = &WhS[s][j2][cQ];
            {   // nt 0..3
                float4 f1 = *(const float4*)r1;
                float4 f2 = *(const float4*)r2;
                MMA_TF32(acc[0], af, __float_as_uint(f1.x), __float_as_uint(f2.x));
                MMA_TF32(acc[1], af, __float_as_uint(f1.y), __float_as_uint(f2.y));
                MMA_TF32(acc[2], af, __float_as_uint(f1.z), __float_as_uint(f2.z));
                MMA_TF32(acc[3], af, __float_as_uint(f1.w), __float_as_uint(f2.w));
            }
            {   // nt 4..7
                float4 f1 = *(const float4*)(r1 + 4);
                float4 f2 = *(const float4*)(r2 + 4);
                MMA_TF32(acc[4], af, __float_as_uint(f1.x), __float_as_uint(f2.x));
                MMA_TF32(acc[5], af, __float_as_uint(f1.y), __float_as_uint(f2.y));
                MMA_TF32(acc[6], af, __float_as_uint(f1.z), __float_as_uint(f2.z));
                MMA_TF32(acc[7], af, __float_as_uint(f1.w), __float_as_uint(f2.w));
            }
        }
        __syncthreads();
    }

    leA += __shfl_xor_sync(0xffffffffu, leA, 1);
    leA += __shfl_xor_sync(0xffffffffu, leA, 2);
    leB += __shfl_xor_sync(0xffffffffu, leB, 1);
    leB += __shfl_xor_sync(0xffffffffu, leB, 2);
    if (c == 0) {
        g_lpart[jh2][sbA] = leA;
        g_lpart[jh2][sbA + 8] = leB;
    }

    // outputs: acc[nt] holds cols nt*8 + 2c (+1) of head h (NORMAL order)
    float* oA = g_part[jh2] + ((size_t)(b * NN + iA)) * 256 + h * HD;
    float* oB = oA + (size_t)8 * 256;
#pragma unroll
    for (int nt = 0; nt < 8; nt++) {
        float2 vA = {acc[nt][0], acc[nt][1]};
        float2 vB = {acc[nt][2], acc[nt][3]};
        *(float2*)&oA[nt * 8 + 2 * c] = vA;
        *(float2*)&oB[nt * 8 + 2 * c] = vB;
    }
}

// ---------------- combine split-j halves (2 float4 per thread for MLP) ----------------
__global__ void reduce_kernel() {
    int idx = blockIdx.x * 256 + threadIdx.x;   // < 262144
    int e4 = idx * 8;
    int node = e4 >> 8, col = e4 & 255;
    int b = node >> 11, n = node & 2047;
    int h = col >> 6;
    int li = b * (HH * NN) + h * NN + n;
    float4 p0a = *(const float4*)&g_part[0][e4];
    float4 p1a = *(const float4*)&g_part[1][e4];
    float4 p0b = *(const float4*)&g_part[0][e4 + 4];
    float4 p1b = *(const float4*)&g_part[1][e4 + 4];
    float l = g_lpart[0][li] + g_lpart[1][li];
    float inv = 1.f / l;
    float4 oa, ob;
    oa.x = (p0a.x + p1a.x) * inv;
    oa.y = (p0a.y + p1a.y) * inv;
    oa.z = (p0a.z + p1a.z) * inv;
    oa.w = (p0a.w + p1a.w) * inv;
    ob.x = (p0b.x + p1b.x) * inv;
    ob.y = (p0b.y + p1b.y) * inv;
    ob.z = (p0b.z + p1b.z) * inv;
    ob.w = (p0b.w + p1b.w) * inv;
    *(float4*)&g_multi[e4] = oa;
    *(float4*)&g_multi[e4 + 4] = ob;
}

// ---------------- launch: kernel launches ONLY ----------------
extern "C" void kernel_launch(void* const* d_in, const int* in_sizes, int n_in,
                              void* d_out, int out_size) {
    const float* x    = (const float*)d_in[0];
    const int*   adj  = (const int*)d_in[1];
    const float* W    = (const float*)d_in[2];
    const float* a    = (const float*)d_in[3];
    const float* Wout = (const float*)d_in[4];
    const float* bout = (const float*)d_in[5];
    float* out = (float*)d_out;

    transpose_kernel<<<256, 256>>>(W, Wout);
    gemm_wh<<<dim3(4, 128), 256>>>(x, a);
    attn_kernel<<<dim3(NN / TI, HH / 2, BB * 2), 128>>>(adj);
    reduce_kernel<<<1024, 256>>>();
    gemm_out<<<dim3(4, 128), 256>>>(out, bout);
}

// round 15
// speedup vs baseline: 1.0798x; 1.0798x over previous
#include <cuda_runtime.h>
#include <math_constants.h>

#define BB 4
#define NN 2048
#define IND 256
#define OUTD 256
#define HH 4
#define HD 64
#define TI 32
#define TJ 32

// ---------------- scratch ----------------
__device__ float g_Wh[BB * NN * OUTD];      // [b*N+n][h*64+d]
__device__ float g_multi[BB * NN * OUTD];
__device__ float g_part[2][BB * NN * OUTD]; // split-j partial accumulators
__device__ float g_lpart[2][BB * HH * NN];  // split-j partial row sums
__device__ float g_ssrc[BB * HH * NN];
__device__ float g_esrP[BB * HH * NN];      // exp(s_src)
__device__ float g_esrN[BB * HH * NN];      // exp(0.2*s_src)
__device__ float4 g_pack[BB * HH * NN];     // (s_dst, exp(s_dst), exp(0.2 s_dst), 0)
__device__ float g_WcatH[IND * OUTD];       // tf32-rounded hi
__device__ float g_WcatL[IND * OUTD];       // tf32 residual lo
__device__ float g_WoutTH[OUTD * OUTD];
__device__ float g_WoutTL[OUTD * OUTD];

__device__ __forceinline__ unsigned tf32r(float x) {
    unsigned u;
    asm("cvt.rna.tf32.f32 %0, %1;" : "=r"(u) : "f"(x));
    return u;
}
__device__ __forceinline__ void cpasync16(unsigned saddr, const void* g) {
    asm volatile("cp.async.cg.shared.global [%0], [%1], 16;" :: "r"(saddr), "l"(g));
}
__device__ __forceinline__ void cpcommit() {
    asm volatile("cp.async.commit_group;" ::: "memory");
}
__device__ __forceinline__ void cpwait1() {
    asm volatile("cp.async.wait_group 1;" ::: "memory");
}
#define MMA_TF32(accv, af, b0, b1)                                              \
    asm volatile(                                                               \
        "mma.sync.aligned.m16n8k8.row.col.f32.tf32.tf32.f32 "                   \
        "{%0,%1,%2,%3}, {%4,%5,%6,%7}, {%8,%9}, {%0,%1,%2,%3};"                 \
        : "+f"(accv[0]), "+f"(accv[1]), "+f"(accv[2]), "+f"(accv[3])            \
        : "r"(af[0]), "r"(af[1]), "r"(af[2]), "r"(af[3]), "r"(b0), "r"(b1))

// ---------------- weight re-layout + tf32 hi/lo split ----------------
__global__ void transpose_kernel(const float* __restrict__ W,
                                 const float* __restrict__ Wout) {
    int idx = blockIdx.x * 256 + threadIdx.x;   // < 65536
    int k = idx >> 8, cc = idx & 255;
    int h = cc >> 6, d = cc & 63;
    float wv = W[h * (IND * HD) + k * HD + d];
    unsigned wh = tf32r(wv);
    g_WcatH[idx] = __uint_as_float(wh);
    g_WcatL[idx] = __uint_as_float(tf32r(wv - __uint_as_float(wh)));
    float ov = Wout[cc * 256 + k];
    unsigned oh = tf32r(ov);
    g_WoutTH[k * 256 + cc] = __uint_as_float(oh);
    g_WoutTL[k * 256 + cc] = __uint_as_float(tf32r(ov - __uint_as_float(oh)));
}

// ---------------- tf32x3 MMA GEMM: 64x64 CTA tile (R11-verified core) ----------------
// FUSE=true (gemm_wh): n-tile == one head; epilogue also emits s-logit tables.
template <bool FUSE>
__device__ __forceinline__ void mma_gemm_body(const float* __restrict__ A,
                                              const float* __restrict__ BH,
                                              const float* __restrict__ BL,
                                              float* __restrict__ C,
                                              const float* __restrict__ bias,
                                              bool has_bias,
                                              const float* __restrict__ avec) {
    __shared__ __align__(16) float As[2][64][20];
    __shared__ __align__(16) float BsH[2][16][72];
    __shared__ __align__(16) float BsL[2][16][72];
    __shared__ float aS[128];
    __shared__ float sred[2][64][2];

    int t = threadIdx.x, lane = t & 31, w = t >> 5;
    int g = lane >> 2, c = lane & 3;
    int mw = w & 3, nw = w >> 2;
    int m0 = blockIdx.y * 64, n0 = blockIdx.x * 64;
    int mb = mw * 16, nb = nw * 32;

    if (FUSE && t < 128) aS[t] = avec[t];

    unsigned asb = (unsigned)__cvta_generic_to_shared(&As[0][0][0]);
    unsigned bhb = (unsigned)__cvta_generic_to_shared(&BsH[0][0][0]);
    unsigned blb = (unsigned)__cvta_generic_to_shared(&BsL[0][0][0]);

    auto stage = [&](int k0, int buf) {
        {
            int row = t >> 2, seg = t & 3;
            cpasync16(asb + buf * 5120 + row * 80 + seg * 16,
                      A + (size_t)(m0 + row) * 256 + k0 + seg * 4);
        }
        {
            int row = t >> 4, seg = t & 15;
            cpasync16(bhb + buf * 4608 + row * 288 + seg * 16,
                      BH + (size_t)(k0 + row) * 256 + n0 + seg * 4);
            cpasync16(blb + buf * 4608 + row * 288 + seg * 16,
                      BL + (size_t)(k0 + row) * 256 + n0 + seg * 4);
        }
    };

    float acc[4][4] = {};

    stage(0, 0);
    cpcommit();
    for (int s = 0; s < 16; s++) {
        int buf = s & 1;
        if (s < 15) stage((s + 1) * 16, buf ^ 1);
        cpcommit();
        cpwait1();
        __syncthreads();
#pragma unroll
        for (int kk = 0; kk < 16; kk += 8) {
            unsigned ah[4], al[4];
#pragma unroll
            for (int q = 0; q < 4; q++) {
                int rr = mb + g + (q & 1) * 8;
                int ck = kk + c + (q >> 1) * 4;
                float v = As[buf][rr][ck];
                unsigned hb = tf32r(v);
                ah[q] = hb;
                al[q] = tf32r(v - __uint_as_float(hb));
            }
#pragma unroll
            for (int ni = 0; ni < 4; ni++) {
                int col = nb + ni * 8 + g;
                unsigned bh0 = __float_as_uint(BsH[buf][kk + c][col]);
                unsigned bh1 = __float_as_uint(BsH[buf][kk + c + 4][col]);
                unsigned bl0 = __float_as_uint(BsL[buf][kk + c][col]);
                unsigned bl1 = __float_as_uint(BsL[buf][kk + c + 4][col]);
                MMA_TF32(acc[ni], al, bh0, bh1);
                MMA_TF32(acc[ni], ah, bl0, bl1);
                MMA_TF32(acc[ni], ah, bh0, bh1);
            }
        }
        __syncthreads();
    }

#pragma unroll
    for (int ni = 0; ni < 4; ni++) {
        int col = n0 + nb + ni * 8 + 2 * c;
        float bx = 0.f, by = 0.f;
        if (has_bias) {
            float2 bv = *(const float2*)&bias[col];
            bx = bv.x; by = bv.y;
        }
        int r0 = m0 + mb + g;
        float2 v0 = {acc[ni][0] + bx, acc[ni][1] + by};
        float2 v1 = {acc[ni][2] + bx, acc[ni][3] + by};
        *(float2*)&C[(size_t)r0 * 256 + col] = v0;
        *(float2*)&C[(size_t)(r0 + 8) * 256 + col] = v1;
    }

    // ---- fused s-logits: this CTA's n-tile is head h = blockIdx.x ----
    if (FUSE) {
        float ps0 = 0.f, ps1 = 0.f, pd0 = 0.f, pd1 = 0.f;
#pragma unroll
        for (int ni = 0; ni < 4; ni++) {
            int c0 = nb + ni * 8 + 2 * c;          // 0..63 within head
            float as0 = aS[c0], as1 = aS[c0 + 1];
            float ad0 = aS[64 + c0], ad1 = aS[64 + c0 + 1];
            ps0 += acc[ni][0] * as0 + acc[ni][1] * as1;
            pd0 += acc[ni][0] * ad0 + acc[ni][1] * ad1;
            ps1 += acc[ni][2] * as0 + acc[ni][3] * as1;
            pd1 += acc[ni][2] * ad0 + acc[ni][3] * ad1;
        }
        ps0 += __shfl_xor_sync(0xffffffffu, ps0, 1);
        ps0 += __shfl_xor_sync(0xffffffffu, ps0, 2);
        pd0 += __shfl_xor_sync(0xffffffffu, pd0, 1);
        pd0 += __shfl_xor_sync(0xffffffffu, pd0, 2);
        ps1 += __shfl_xor_sync(0xffffffffu, ps1, 1);
        ps1 += __shfl_xor_sync(0xffffffffu, ps1, 2);
        pd1 += __shfl_xor_sync(0xffffffffu, pd1, 1);
        pd1 += __shfl_xor_sync(0xffffffffu, pd1, 2);
        if (c == 0) {
            sred[nw][mb + g][0] = ps0;
            sred[nw][mb + g][1] = pd0;
            sred[nw][mb + g + 8][0] = ps1;
            sred[nw][mb + g + 8][1] = pd1;
        }
        __syncthreads();
        if (t < 64) {
            float ss = sred[0][t][0] + sred[1][t][0];
            float sd = sred[0][t][1] + sred[1][t][1];
            int node = m0 + t;
            int b = node >> 11, n = node & 2047;
            int h = blockIdx.x;
            int idx = b * (HH * NN) + h * NN + n;
            g_ssrc[idx] = ss;
            g_esrP[idx] = __expf(ss);
            g_esrN[idx] = __expf(0.2f * ss);
            float4 pk = {sd, __expf(sd), __expf(0.2f * sd), 0.f};
            g_pack[idx] = pk;
        }
    }
}

__global__ void __launch_bounds__(256, 3) gemm_wh(const float* __restrict__ x,
                                                  const float* __restrict__ a) {
    mma_gemm_body<true>(x, g_WcatH, g_WcatL, g_Wh, nullptr, false, a);
}
__global__ void __launch_bounds__(256, 3) gemm_out(float* __restrict__ out,
                                                   const float* __restrict__ bout) {
    mma_gemm_body<false>(g_multi, g_WoutTH, g_WoutTL, out, bout, true, nullptr);
}

// ---------------- attention: split-j (R12/R13-verified, byte-identical) ----------------
__global__ void __launch_bounds__(128) attn_kernel(const int* __restrict__ adj) {
    __shared__ __align__(16) float  WhS[2][TJ][136];
    __shared__ __align__(16) int    adjS[2][TJ][36];
    __shared__ float4 packS[2][2][TJ];

    int t = threadIdx.x;
    int lane = t & 31;
    int w = t >> 5;
    int hl = w & 1, is = w >> 1;
    int g = lane >> 2, c = lane & 3;

    int zz = blockIdx.z;
    int b = zz & (BB - 1);
    int jh2 = zz >> 2;
    int h0 = blockIdx.y * 2;
    int i0 = blockIdx.x * TI;
    int h = h0 + hl;

    int iA = i0 + is * 16 + g;
    int sbA = b * (HH * NN) + h * NN + iA;
    float siA = g_ssrc[sbA],     ePA = g_esrP[sbA],     eNA = g_esrN[sbA];
    float siB = g_ssrc[sbA + 8], ePB = g_esrP[sbA + 8], eNB = g_esrN[sbA + 8];

    float acc[8][4];
#pragma unroll
    for (int nt = 0; nt < 8; nt++)
#pragma unroll
        for (int q = 0; q < 4; q++) acc[nt][q] = 0.f;
    float leA = 0.f, leB = 0.f;

    const float* WhB = g_Wh + (size_t)b * NN * 256 + h0 * HD;
    const int* adjB = adj + ((size_t)(b * NN + i0)) * NN;
    const float4* packB = g_pack + b * (HH * NN);

    unsigned whsb  = (unsigned)__cvta_generic_to_shared(&WhS[0][0][0]);
    unsigned adjsb = (unsigned)__cvta_generic_to_shared(&adjS[0][0][0]);
    unsigned pksb  = (unsigned)__cvta_generic_to_shared(&packS[0][0][0]);
    const unsigned WHSZ = TJ * 136 * 4, ADSZ = TJ * 36 * 4, PKSZ = 2 * TJ * 16;

    int isg = is * 16 + g;
    int tile0 = jh2 * (NN / TJ / 2);
    int tile1 = tile0 + NN / TJ / 2;

    auto stage = [&](int j0, int s) {
        unsigned wb = whsb + s * WHSZ;
#pragma unroll
        for (int k = 0; k < 8; k++) {
            int id = t + k * 128;
            int row = id >> 5, seg = id & 31;
            cpasync16(wb + row * 544 + seg * 16,
                      WhB + (size_t)(j0 + row) * 256 + seg * 4);
        }
        unsigned ab = adjsb + s * ADSZ;
#pragma unroll
        for (int k = 0; k < 2; k++) {
            int id = t + k * 128;
            int row = id >> 3, seg = id & 7;
            cpasync16(ab + row * 144 + seg * 16,
                      adjB + (size_t)row * NN + j0 + seg * 4);
        }
        if (t < 64) {
            int hh = t >> 5, jj = t & 31;
            cpasync16(pksb + s * PKSZ + t * 16,
                      packB + (h0 + hh) * NN + j0 + jj);
        }
    };

    stage(tile0 * TJ, 0);
    cpcommit();

    for (int tile = tile0; tile < tile1; tile++) {
        int s = tile & 1;
        if (tile + 1 < tile1) stage((tile + 1) * TJ, s ^ 1);
        cpcommit();
        cpwait1();
        __syncthreads();

#pragma unroll
        for (int kc = 0; kc < 4; kc++) {
            int j1 = kc * 8 + c, j2 = j1 + 4;
            float4 P1 = packS[s][hl][j1];
            float4 P2 = packS[s][hl][j2];
            int aA1 = adjS[s][isg][j1],     aA2 = adjS[s][isg][j2];
            int aB1 = adjS[s][isg + 8][j1], aB2 = adjS[s][isg + 8][j2];
            float e0 = (siA + P1.x > 0.f) ? ePA * P1.y : eNA * P1.z;
            float e1 = (siB + P1.x > 0.f) ? ePB * P1.y : eNB * P1.z;
            float e2 = (siA + P2.x > 0.f) ? ePA * P2.y : eNA * P2.z;
            float e3 = (siB + P2.x > 0.f) ? ePB * P2.y : eNB * P2.z;
            e0 = aA1 ? e0 : 0.f;
            e1 = aB1 ? e1 : 0.f;
            e2 = aA2 ? e2 : 0.f;
            e3 = aB2 ? e3 : 0.f;
            leA += e0 + e2;
            leB += e1 + e3;
            unsigned a0 = tf32r(e0), a1 = tf32r(e1), a2 = tf32r(e2), a3 = tf32r(e3);
            const float* r1 = &WhS[s][j1][hl * 64 + g];
            const float* r2 = &WhS[s][j2][hl * 64 + g];
#pragma unroll
            for (int nt = 0; nt < 8; nt++) {
                unsigned b0 = __float_as_uint(r1[nt * 8]);
                unsigned b1 = __float_as_uint(r2[nt * 8]);
                asm volatile(
                    "mma.sync.aligned.m16n8k8.row.col.f32.tf32.tf32.f32 "
                    "{%0,%1,%2,%3}, {%4,%5,%6,%7}, {%8,%9}, {%0,%1,%2,%3};"
                    : "+f"(acc[nt][0]), "+f"(acc[nt][1]), "+f"(acc[nt][2]), "+f"(acc[nt][3])
                    : "r"(a0), "r"(a1), "r"(a2), "r"(a3), "r"(b0), "r"(b1));
            }
        }
        __syncthreads();
    }

    leA += __shfl_xor_sync(0xffffffffu, leA, 1);
    leA += __shfl_xor_sync(0xffffffffu, leA, 2);
    leB += __shfl_xor_sync(0xffffffffu, leB, 1);
    leB += __shfl_xor_sync(0xffffffffu, leB, 2);
    if (c == 0) {
        g_lpart[jh2][sbA] = leA;
        g_lpart[jh2][sbA + 8] = leB;
    }

    float* oA = g_part[jh2] + ((size_t)(b * NN + iA)) * 256 + h * HD;
    float* oB = oA + (size_t)8 * 256;
#pragma unroll
    for (int nt = 0; nt < 8; nt++) {
        float2 vA = {acc[nt][0], acc[nt][1]};
        float2 vB = {acc[nt][2], acc[nt][3]};
        *(float2*)&oA[nt * 8 + 2 * c] = vA;
        *(float2*)&oB[nt * 8 + 2 * c] = vB;
    }
}

// ---------------- combine split-j halves (R14-verified: 2 float4/thread) ----------------
__global__ void reduce_kernel() {
    int idx = blockIdx.x * 256 + threadIdx.x;   // < 262144
    int e4 = idx * 8;
    int node = e4 >> 8, col = e4 & 255;
    int b = node >> 11, n = node & 2047;
    int h = col >> 6;
    int li = b * (HH * NN) + h * NN + n;
    float4 p0a = *(const float4*)&g_part[0][e4];
    float4 p1a = *(const float4*)&g_part[1][e4];
    float4 p0b = *(const float4*)&g_part[0][e4 + 4];
    float4 p1b = *(const float4*)&g_part[1][e4 + 4];
    float l = g_lpart[0][li] + g_lpart[1][li];
    float inv = 1.f / l;
    float4 oa, ob;
    oa.x = (p0a.x + p1a.x) * inv;
    oa.y = (p0a.y + p1a.y) * inv;
    oa.z = (p0a.z + p1a.z) * inv;
    oa.w = (p0a.w + p1a.w) * inv;
    ob.x = (p0b.x + p1b.x) * inv;
    ob.y = (p0b.y + p1b.y) * inv;
    ob.z = (p0b.z + p1b.z) * inv;
    ob.w = (p0b.w + p1b.w) * inv;
    *(float4*)&g_multi[e4] = oa;
    *(float4*)&g_multi[e4 + 4] = ob;
}

// ---------------- launch: kernel launches ONLY ----------------
extern "C" void kernel_launch(void* const* d_in, const int* in_sizes, int n_in,
                              void* d_out, int out_size) {
    const float* x    = (const float*)d_in[0];
    const int*   adj  = (const int*)d_in[1];
    const float* W    = (const float*)d_in[2];
    const float* a    = (const float*)d_in[3];
    const float* Wout = (const float*)d_in[4];
    const float* bout = (const float*)d_in[5];
    float* out = (float*)d_out;

    transpose_kernel<<<256, 256>>>(W, Wout);
    gemm_wh<<<dim3(4, 128), 256>>>(x, a);
    attn_kernel<<<dim3(NN / TI, HH / 2, BB * 2), 128>>>(adj);
    reduce_kernel<<<1024, 256>>>();
    gemm_out<<<dim3(4, 128), 256>>>(out, bout);
}